// round 12
// baseline (speedup 1.0000x reference)
#include <cuda_runtime.h>
#include <cuda_bf16.h>
#include <cstdint>

#define B_  4
#define S_  2048
#define D_  1024
#define H_  16
#define HD_ 64
#define TD_ 3072   // 3*D
#define NQKV (B_ * H_ * S_ * HD_)   // 8,388,608

// ---------------- scratch: hi/lo bf16 split tensors --------------------------
__device__ __nv_bfloat16 g_xh[B_ * S_ * D_],  g_xl[B_ * S_ * D_];
__device__ __nv_bfloat16 g_wqh[TD_ * D_],     g_wql[TD_ * D_];
__device__ __nv_bfloat16 g_woh[D_ * D_],      g_wol[D_ * D_];
__device__ __nv_bfloat16 g_qh[NQKV], g_ql[NQKV];
__device__ __nv_bfloat16 g_kh[NQKV], g_kl[NQKV];
__device__ __nv_bfloat16 g_vh[NQKV], g_vl[NQKV];
__device__ __nv_bfloat16 g_vfh[B_ * S_ * D_], g_vfl[B_ * S_ * D_];

// ---------------- fast exp (5-FMA poly) --------------------------------------
__device__ __forceinline__ float fexp(float x) {
    x = fmaxf(x, -80.0f);
    float y = x * 1.44269504088896340736f;
    float t = y + 12582912.0f;
    int   i = __float_as_int(t) - 0x4b400000;
    float f = y - (t - 12582912.0f);
    float p =              1.33336500e-3f;
    p = fmaf(p, f,         9.61793571e-3f);
    p = fmaf(p, f,         5.55041086e-2f);
    p = fmaf(p, f,         2.40226507e-1f);
    p = fmaf(p, f,         6.93147181e-1f);
    p = fmaf(p, f,         1.0f);
    return __int_as_float(__float_as_int(p) + (i << 23));
}

// ---------------- helpers ----------------------------------------------------
__device__ __forceinline__ void split1(float x, __nv_bfloat16& h, __nv_bfloat16& l) {
    h = __float2bfloat16_rn(x);
    l = __float2bfloat16_rn(x - __bfloat162float(h));
}
__device__ __forceinline__ uint32_t pckh(__nv_bfloat16 a, __nv_bfloat16 b) {
    __nv_bfloat162 t = __halves2bfloat162(a, b);
    return *reinterpret_cast<uint32_t*>(&t);
}
__device__ __forceinline__ void mma16816(float c[4], const uint32_t a[4], const uint32_t b[2]) {
    asm volatile(
        "mma.sync.aligned.m16n8k16.row.col.f32.bf16.bf16.f32 "
        "{%0,%1,%2,%3}, {%4,%5,%6,%7}, {%8,%9}, {%0,%1,%2,%3};"
        : "+f"(c[0]), "+f"(c[1]), "+f"(c[2]), "+f"(c[3])
        : "r"(a[0]), "r"(a[1]), "r"(a[2]), "r"(a[3]), "r"(b[0]), "r"(b[1]));
}
__device__ __forceinline__ uint32_t smem_u32(const void* p) {
    uint32_t a;
    asm("{ .reg .u64 t; cvta.to.shared.u64 t, %1; cvt.u32.u64 %0, t; }" : "=r"(a) : "l"(p));
    return a;
}
__device__ __forceinline__ void cpa16(uint32_t d, const void* s) {
    asm volatile("cp.async.cg.shared.global [%0], [%1], 16;" :: "r"(d), "l"(s));
}
#define CP_COMMIT() asm volatile("cp.async.commit_group;" ::: "memory")
#define CP_WAIT0()  asm volatile("cp.async.wait_group 0;" ::: "memory")

__device__ __forceinline__ void ldsm4(uint32_t* r, uint32_t a) {
    asm volatile("ldmatrix.sync.aligned.m8n8.x4.shared.b16 {%0,%1,%2,%3}, [%4];"
        : "=r"(r[0]), "=r"(r[1]), "=r"(r[2]), "=r"(r[3]) : "r"(a));
}
__device__ __forceinline__ void ldsm4t(uint32_t* r, uint32_t a) {
    asm volatile("ldmatrix.sync.aligned.m8n8.x4.trans.shared.b16 {%0,%1,%2,%3}, [%4];"
        : "=r"(r[0]), "=r"(r[1]), "=r"(r[2]), "=r"(r[3]) : "r"(a));
}

// ================= pre-split: fp32 -> (hi, lo) bf16 ==========================
__global__ void split_kernel(const float* __restrict__ src,
                             __nv_bfloat16* __restrict__ dh,
                             __nv_bfloat16* __restrict__ dl, int n4)
{
    int i = blockIdx.x * blockDim.x + threadIdx.x;
    if (i >= n4) return;
    float4 v = ((const float4*)src)[i];
    __nv_bfloat16 h0,h1,h2,h3,l0,l1,l2,l3;
    split1(v.x,h0,l0); split1(v.y,h1,l1); split1(v.z,h2,l2); split1(v.w,h3,l3);
    ((uint2*)dh)[i] = make_uint2(pckh(h0,h1), pckh(h2,h3));
    ((uint2*)dl)[i] = make_uint2(pckh(l0,l1), pckh(l2,l3));
}

// ================= HMMA split-bf16 GEMM, 2-stage cp.async, 2 CTA/SM =========
#define GSTK 40
#define GTILE (128 * GSTK)
#define GSTAGE (4 * GTILE)
#define GSM_TOTAL (2 * GSTAGE * 2)   // 81920 bytes

template <int EPI>
__global__ void __launch_bounds__(256, 2)
hgemm_kernel(const __nv_bfloat16* __restrict__ Ah, const __nv_bfloat16* __restrict__ Al,
             const __nv_bfloat16* __restrict__ Wh, const __nv_bfloat16* __restrict__ Wl,
             const float* __restrict__ bias, float* __restrict__ C,
             int M, int N, int K)
{
    extern __shared__ __nv_bfloat16 gsm[];
    const uint32_t sb = smem_u32(gsm);

    const int tid = threadIdx.x;
    const int w = tid >> 5, lane = tid & 31;
    const int gid = lane >> 2, tig = lane & 3;
    const int wm = w & 3, wn = w >> 2;
    const int m0 = blockIdx.y * 128, n0 = blockIdx.x * 128;

    const int lrow = tid >> 1;
    const int lcol = (tid & 1) * 16;

    const uint32_t aoffG = (uint32_t)(((lane & 15) * GSTK + ((lane >> 4) << 3)) * 2);
    const uint32_t boffG = (uint32_t)(((((lane >> 4) << 3) + (lane & 7)) * GSTK
                                      + (((lane >> 3) & 1) << 3)) * 2);

    float acc[2][8][4];
#pragma unroll
    for (int mi = 0; mi < 2; mi++)
#pragma unroll
        for (int ni = 0; ni < 8; ni++)
            acc[mi][ni][0]=acc[mi][ni][1]=acc[mi][ni][2]=acc[mi][ni][3]=0.f;

    const __nv_bfloat16* srcA[4] = {
        Ah + (size_t)(m0 + lrow) * K + lcol,
        Al + (size_t)(m0 + lrow) * K + lcol,
        Wh + (size_t)(n0 + lrow) * K + lcol,
        Wl + (size_t)(n0 + lrow) * K + lcol };

    const int NIT = K / 32;
    auto issue = [&](int st, int k0) {
#pragma unroll
        for (int tI = 0; tI < 4; tI++) {
            uint32_t d = sb + (st * GSTAGE + tI * GTILE + lrow * GSTK + lcol) * 2;
            const __nv_bfloat16* s = srcA[tI] + k0;
            cpa16(d, s);
            cpa16(d + 16, s + 8);
        }
    };

    issue(0, 0); CP_COMMIT();

    for (int kt = 0; kt < NIT; kt++) {
        CP_WAIT0();
        __syncthreads();
        if (kt + 1 < NIT) issue((kt + 1) & 1, (kt + 1) * 32);
        CP_COMMIT();

        const uint32_t stb = sb + (uint32_t)((kt & 1) * GSTAGE * 2);
        const uint32_t stAh = stb, stAl = stb + GTILE * 2;
        const uint32_t stWh = stb + 2 * GTILE * 2, stWl = stb + 3 * GTILE * 2;

#pragma unroll
        for (int kk = 0; kk < 2; kk++) {
            const int qc0 = kk * 16;
            uint32_t aH[2][4], aL[2][4];
#pragma unroll
            for (int mi = 0; mi < 2; mi++) {
                uint32_t ro = (uint32_t)(((wm * 32 + mi * 16) * GSTK + qc0) * 2);
                ldsm4(aH[mi], stAh + ro + aoffG);
                ldsm4(aL[mi], stAl + ro + aoffG);
            }
#pragma unroll
            for (int nj = 0; nj < 4; nj++) {
                uint32_t bh4[4], bl4[4];
                uint32_t no = (uint32_t)(((wn * 64 + nj * 16) * GSTK + qc0) * 2);
                ldsm4(bh4, stWh + no + boffG);
                ldsm4(bl4, stWl + no + boffG);
#pragma unroll
                for (int mi = 0; mi < 2; mi++) {
                    mma16816(acc[mi][2*nj],   aH[mi], bh4);
                    mma16816(acc[mi][2*nj],   aH[mi], bl4);
                    mma16816(acc[mi][2*nj],   aL[mi], bh4);
                    mma16816(acc[mi][2*nj+1], aH[mi], bh4 + 2);
                    mma16816(acc[mi][2*nj+1], aH[mi], bl4 + 2);
                    mma16816(acc[mi][2*nj+1], aL[mi], bh4 + 2);
                }
            }
        }
    }

    // epilogue
#pragma unroll
    for (int mi = 0; mi < 2; mi++) {
#pragma unroll
        for (int rr = 0; rr < 2; rr++) {
            int m = m0 + wm * 32 + mi * 16 + gid + rr * 8;
#pragma unroll
            for (int ni = 0; ni < 8; ni++) {
                int n = n0 + wn * 64 + ni * 8 + tig * 2;
                float v0 = acc[mi][ni][rr*2+0] + bias[n];
                float v1 = acc[mi][ni][rr*2+1] + bias[n+1];
                if (EPI == 0) {
                    *(float2*)(C + (size_t)m * N + n) = make_float2(v0, v1);
                } else {
                    int h  = n / 192;
                    int r2 = n - h * 192;
                    int wch = r2 >> 6;
                    int hd = r2 & 63;
                    int bb = m >> 11, ss = m & (S_ - 1);
                    size_t di = ((size_t)(bb * H_ + h) * S_ + ss) * HD_ + hd;
                    __nv_bfloat16* dh = (wch == 0) ? g_qh : (wch == 1) ? g_kh : g_vh;
                    __nv_bfloat16* dl = (wch == 0) ? g_ql : (wch == 1) ? g_kl : g_vl;
                    __nv_bfloat16 h0,h1,l0,l1;
                    split1(v0,h0,l0); split1(v1,h1,l1);
                    *(uint32_t*)(dh + di) = pckh(h0,h1);
                    *(uint32_t*)(dl + di) = pckh(l0,l1);
                }
            }
        }
    }
}

// ---------------- attention smem (bf16 elems), stride 72 ---------------------
#define STK 72
#define ASM_ELEMS 55296          // 110592 bytes

// ================= attention: HMMA split-bf16 + ldmatrix, 2 CTA/SM ==========
__global__ void __launch_bounds__(256, 2)
attn_mma_kernel(float* __restrict__ gAttn, int writeAttn)
{
    extern __shared__ __nv_bfloat16 sm[];
    const uint32_t sb = smem_u32(sm);
    const uint32_t sbQH = sb, sbQL = sb + 18432;
    const uint32_t sbK  = sb + 36864;          // + st*18432 ; KL at +9216
    const uint32_t sbV  = sb + 73728;          // + st*18432 ; VL at +9216

    const int tid = threadIdx.x;
    const int w = tid >> 5, lane = tid & 31;
    const int gid = lane >> 2, tig = lane & 3;
    const int qt = blockIdx.x, bh = blockIdx.y;
    const int sq = qt * 128;

    const size_t qoff = ((size_t)bh * S_ + sq) * HD_;
    const size_t koff = (size_t)bh * S_ * HD_;

    const uint32_t aoff = (uint32_t)(((lane & 15) * STK + ((lane >> 4) << 3)) * 2);
    const uint32_t boff = (uint32_t)(((((lane >> 4) << 3) + (lane & 7)) * STK
                                     + (((lane >> 3) & 1) << 3)) * 2);
    const uint32_t voff = (uint32_t)((((((lane >> 3) & 1) << 3) + (lane & 7)) * STK
                                     + ((lane >> 4) << 3)) * 2);

    auto issueK = [&](int st, int t) {
        const __nv_bfloat16* kh = g_kh + koff + t * 4096;
        const __nv_bfloat16* kl = g_kl + koff + t * 4096;
        uint32_t base = sbK + st * 18432;
#pragma unroll
        for (int it = 0; it < 2; it++) {
            int c = it * 256 + tid;
            int row = c >> 3, k8 = (c & 7) * 8;
            uint32_t d = base + (uint32_t)((row * STK + k8) * 2);
            cpa16(d,        kh + row * 64 + k8);
            cpa16(d + 9216, kl + row * 64 + k8);
        }
    };
    auto issueV = [&](int st, int t) {
        const __nv_bfloat16* vh = g_vh + koff + t * 4096;
        const __nv_bfloat16* vl = g_vl + koff + t * 4096;
        uint32_t base = sbV + st * 18432;
#pragma unroll
        for (int it = 0; it < 2; it++) {
            int c = it * 256 + tid;
            int row = c >> 3, k8 = (c & 7) * 8;
            uint32_t d = base + (uint32_t)((row * STK + k8) * 2);
            cpa16(d,        vh + row * 64 + k8);
            cpa16(d + 9216, vl + row * 64 + k8);
        }
    };

    // ---- load Q tile (128x64) hi/lo to smem --------------------------------
    {
        __nv_bfloat16* Qhs = sm;
        __nv_bfloat16* Qls = sm + 18432 / 2;   // == sm + 9216 elems
#pragma unroll
        for (int it = 0; it < 8; it++) {
            int f4 = it * 256 + tid;
            int r = f4 >> 4, c = (f4 & 15) << 2;
            *(uint2*)&Qhs[r*STK + c] = ((const uint2*)(g_qh + qoff))[f4];
            *(uint2*)&Qls[r*STK + c] = ((const uint2*)(g_ql + qoff))[f4];
        }
    }
    issueK(0, 0); CP_COMMIT();
    __syncthreads();

    const int qr = w * 16 + gid;
    float m0 = -1e30f, m1 = -1e30f, l0s = 0.f, l1s = 0.f;

    // =================== pass 1: rowmax m, denom l ===========================
    for (int t = 0; t < 32; t++) {
        CP_WAIT0();
        __syncthreads();
        if (t + 1 < 32) issueK((t + 1) & 1, t + 1);
        CP_COMMIT();

        const uint32_t stKh = sbK + (t & 1) * 18432;
        const uint32_t stKl = stKh + 9216;

        float s[8][4];
#pragma unroll
        for (int nc = 0; nc < 8; nc++)
            s[nc][0]=s[nc][1]=s[nc][2]=s[nc][3]=0.f;

#pragma unroll
        for (int kc = 0; kc < 4; kc++) {
            uint32_t ro = (uint32_t)(((w * 16) * STK + kc * 16) * 2);
            uint32_t qh4[4], ql4[4];
            ldsm4(qh4, sbQH + ro + aoff);
            ldsm4(ql4, sbQL + ro + aoff);
            const uint32_t co = (uint32_t)(kc * 16 * 2);
#pragma unroll
            for (int nj = 0; nj < 4; nj++) {
                uint32_t bh4[4], bl4[4];
                uint32_t no = (uint32_t)((nj * 16 * STK) * 2) + co;
                ldsm4(bh4, stKh + no + boff);
                ldsm4(bl4, stKl + no + boff);
                mma16816(s[2*nj],   qh4, bh4);
                mma16816(s[2*nj],   qh4, bl4);
                mma16816(s[2*nj],   ql4, bh4);
                mma16816(s[2*nj+1], qh4, bh4 + 2);
                mma16816(s[2*nj+1], qh4, bl4 + 2);
                mma16816(s[2*nj+1], ql4, bh4 + 2);
            }
        }

        float mx0 = -1e30f, mx1 = -1e30f;
#pragma unroll
        for (int nc = 0; nc < 8; nc++) {
            s[nc][0]*=0.125f; s[nc][1]*=0.125f; s[nc][2]*=0.125f; s[nc][3]*=0.125f;
            mx0 = fmaxf(mx0, fmaxf(s[nc][0], s[nc][1]));
            mx1 = fmaxf(mx1, fmaxf(s[nc][2], s[nc][3]));
        }
        mx0 = fmaxf(mx0, __shfl_xor_sync(0xffffffffu, mx0, 1));
        mx0 = fmaxf(mx0, __shfl_xor_sync(0xffffffffu, mx0, 2));
        mx1 = fmaxf(mx1, __shfl_xor_sync(0xffffffffu, mx1, 1));
        mx1 = fmaxf(mx1, __shfl_xor_sync(0xffffffffu, mx1, 2));
        float mn0 = fmaxf(m0, mx0), mn1 = fmaxf(m1, mx1);
        float ps0 = 0.f, ps1 = 0.f;
#pragma unroll
        for (int nc = 0; nc < 8; nc++) {
            ps0 += fexp(s[nc][0]-mn0) + fexp(s[nc][1]-mn0);
            ps1 += fexp(s[nc][2]-mn1) + fexp(s[nc][3]-mn1);
        }
        ps0 += __shfl_xor_sync(0xffffffffu, ps0, 1);
        ps0 += __shfl_xor_sync(0xffffffffu, ps0, 2);
        ps1 += __shfl_xor_sync(0xffffffffu, ps1, 1);
        ps1 += __shfl_xor_sync(0xffffffffu, ps1, 2);
        l0s = l0s * fexp(m0 - mn0) + ps0;  m0 = mn0;
        l1s = l1s * fexp(m1 - mn1) + ps1;  m1 = mn1;
    }
    const float invl0 = 1.0f / l0s;
    const float invl1 = 1.0f / l1s;

    float o[8][4];
#pragma unroll
    for (int nd = 0; nd < 8; nd++)
        o[nd][0]=o[nd][1]=o[nd][2]=o[nd][3]=0.f;

    issueK(0, 0); issueV(0, 0); CP_COMMIT();

    // =================== pass 2: normalized P out + O = P@V ==================
    for (int t = 0; t < 32; t++) {
        CP_WAIT0();
        __syncthreads();
        if (t + 1 < 32) { issueK((t + 1) & 1, t + 1); issueV((t + 1) & 1, t + 1); }
        CP_COMMIT();

        const uint32_t stKh = sbK + (t & 1) * 18432;
        const uint32_t stKl = stKh + 9216;
        const uint32_t stVh = sbV + (t & 1) * 18432;
        const uint32_t stVl = stVh + 9216;

        float s[8][4];
#pragma unroll
        for (int nc = 0; nc < 8; nc++)
            s[nc][0]=s[nc][1]=s[nc][2]=s[nc][3]=0.f;

#pragma unroll
        for (int kc = 0; kc < 4; kc++) {
            uint32_t ro = (uint32_t)(((w * 16) * STK + kc * 16) * 2);
            uint32_t qh4[4], ql4[4];
            ldsm4(qh4, sbQH + ro + aoff);
            ldsm4(ql4, sbQL + ro + aoff);
            const uint32_t co = (uint32_t)(kc * 16 * 2);
#pragma unroll
            for (int nj = 0; nj < 4; nj++) {
                uint32_t bh4[4], bl4[4];
                uint32_t no = (uint32_t)((nj * 16 * STK) * 2) + co;
                ldsm4(bh4, stKh + no + boff);
                ldsm4(bl4, stKl + no + boff);
                mma16816(s[2*nj],   qh4, bh4);
                mma16816(s[2*nj],   qh4, bl4);
                mma16816(s[2*nj],   ql4, bh4);
                mma16816(s[2*nj+1], qh4, bh4 + 2);
                mma16816(s[2*nj+1], qh4, bl4 + 2);
                mma16816(s[2*nj+1], ql4, bh4 + 2);
            }
        }

#pragma unroll
        for (int nc = 0; nc < 8; nc++) {
            s[nc][0] = fexp(s[nc][0]*0.125f - m0) * invl0;
            s[nc][1] = fexp(s[nc][1]*0.125f - m0) * invl0;
            s[nc][2] = fexp(s[nc][2]*0.125f - m1) * invl1;
            s[nc][3] = fexp(s[nc][3]*0.125f - m1) * invl1;
        }

        if (writeAttn) {
            float* gA = gAttn + ((size_t)bh * S_ + sq + qr) * S_ + t*64 + tig*2;
#pragma unroll
            for (int nc = 0; nc < 8; nc++) {
                *(float2*)(gA + nc*8)        = make_float2(s[nc][0], s[nc][1]);
                *(float2*)(gA + 8*S_ + nc*8) = make_float2(s[nc][2], s[nc][3]);
            }
        }

        // PV: A-frags from S accumulators; B-frags via ldmatrix.trans on V
#pragma unroll
        for (int kc = 0; kc < 4; kc++) {
            uint32_t aH[4], aL[4];
            {
                const float* p0 = s[2*kc];
                const float* p1 = s[2*kc+1];
                __nv_bfloat16 h00,h01,h02,h03,h10,h11,h12,h13;
                __nv_bfloat16 q00,q01,q02,q03,q10,q11,q12,q13;
                split1(p0[0],h00,q00); split1(p0[1],h01,q01);
                split1(p0[2],h02,q02); split1(p0[3],h03,q03);
                split1(p1[0],h10,q10); split1(p1[1],h11,q11);
                split1(p1[2],h12,q12); split1(p1[3],h13,q13);
                aH[0]=pckh(h00,h01); aH[1]=pckh(h02,h03);
                aH[2]=pckh(h10,h11); aH[3]=pckh(h12,h13);
                aL[0]=pckh(q00,q01); aL[1]=pckh(q02,q03);
                aL[2]=pckh(q10,q11); aL[3]=pckh(q12,q13);
            }
            const uint32_t ko = (uint32_t)((kc * 16 * STK) * 2);
#pragma unroll
            for (int nj = 0; nj < 4; nj++) {
                uint32_t vh4[4], vl4[4];
                uint32_t no = ko + (uint32_t)(nj * 16 * 2);
                ldsm4t(vh4, stVh + no + voff);
                ldsm4t(vl4, stVl + no + voff);
                mma16816(o[2*nj],   aH, vh4);
                mma16816(o[2*nj],   aH, vl4);
                mma16816(o[2*nj],   aL, vh4);
                mma16816(o[2*nj+1], aH, vh4 + 2);
                mma16816(o[2*nj+1], aH, vl4 + 2);
                mma16816(o[2*nj+1], aL, vh4 + 2);
            }
        }
    }

    // O -> hi/lo bf16 in [B,H,S,hd] layout (== the buggy reshape) for out GEMM
    {
        size_t ob = ((size_t)bh * S_ + sq + qr) * HD_ + tig*2;
#pragma unroll
        for (int nd = 0; nd < 8; nd++) {
            __nv_bfloat16 h0,h1,h2,h3,l0,l1,l2,l3;
            split1(o[nd][0],h0,l0); split1(o[nd][1],h1,l1);
            split1(o[nd][2],h2,l2); split1(o[nd][3],h3,l3);
            *(uint32_t*)(g_vfh + ob + nd*8)          = pckh(h0,h1);
            *(uint32_t*)(g_vfl + ob + nd*8)          = pckh(l0,l1);
            *(uint32_t*)(g_vfh + ob + 8*HD_ + nd*8)  = pckh(h2,h3);
            *(uint32_t*)(g_vfl + ob + 8*HD_ + nd*8)  = pckh(l2,l3);
        }
    }
}

// ---------------------------------------------------------------------------
extern "C" void kernel_launch(void* const* d_in, const int* in_sizes, int n_in,
                              void* d_out, int out_size)
{
    const float* x     = (const float*)d_in[0];
    const float* w_qkv = (const float*)d_in[1];
    const float* b_qkv = (const float*)d_in[2];
    const float* w_out = (const float*)d_in[3];
    const float* b_out = (const float*)d_in[4];
    float* out = (float*)d_out;

    const long long BSD  = (long long)B_ * S_ * D_;
    const long long BHSS = (long long)B_ * H_ * S_ * S_;

    float* outp = nullptr;
    float* attnp = nullptr;
    int wA = 0;
    if ((long long)out_size >= BSD + BHSS) { outp = out; attnp = out + BSD; wA = 1; }
    else if ((long long)out_size == BHSS)  { attnp = out; wA = 1; }
    else                                   { outp = out; }

    cudaFuncSetAttribute(attn_mma_kernel, cudaFuncAttributeMaxDynamicSharedMemorySize,
                         ASM_ELEMS * (int)sizeof(__nv_bfloat16));
    cudaFuncSetAttribute(hgemm_kernel<0>, cudaFuncAttributeMaxDynamicSharedMemorySize,
                         GSM_TOTAL);
    cudaFuncSetAttribute(hgemm_kernel<1>, cudaFuncAttributeMaxDynamicSharedMemorySize,
                         GSM_TOTAL);

    __nv_bfloat16 *xh, *xl, *wqh, *wql, *woh, *wol, *vfh, *vfl;
    cudaGetSymbolAddress((void**)&xh,  g_xh);  cudaGetSymbolAddress((void**)&xl,  g_xl);
    cudaGetSymbolAddress((void**)&wqh, g_wqh); cudaGetSymbolAddress((void**)&wql, g_wql);
    cudaGetSymbolAddress((void**)&woh, g_woh); cudaGetSymbolAddress((void**)&wol, g_wol);
    cudaGetSymbolAddress((void**)&vfh, g_vfh); cudaGetSymbolAddress((void**)&vfl, g_vfl);

    // K0: pre-split fp32 -> hi/lo bf16
    {
        int n4x = (B_ * S_ * D_) / 4, n4q = (TD_ * D_) / 4, n4o = (D_ * D_) / 4;
        split_kernel<<<(n4x + 255) / 256, 256>>>(x,     xh,  xl,  n4x);
        split_kernel<<<(n4q + 255) / 256, 256>>>(w_qkv, wqh, wql, n4q);
        split_kernel<<<(n4o + 255) / 256, 256>>>(w_out, woh, wol, n4o);
    }
    // K1: fused QKV projection (HMMA + ldmatrix, 2 CTA/SM)
    {
        dim3 grid(TD_ / 128, (B_ * S_) / 128);
        hgemm_kernel<1><<<grid, 256, GSM_TOTAL>>>(xh, xl, wqh, wql, b_qkv, nullptr,
                                                  B_ * S_, TD_, D_);
    }
    // K2: HMMA attention (2 CTA/SM)
    {
        dim3 grid(S_ / 128, B_ * H_);
        attn_mma_kernel<<<grid, 256, ASM_ELEMS * (int)sizeof(__nv_bfloat16)>>>(attnp, wA);
    }
    // K3: output projection
    if (outp) {
        dim3 grid(D_ / 128, (B_ * S_) / 128);
        hgemm_kernel<0><<<grid, 256, GSM_TOTAL>>>(vfh, vfl, woh, wol, b_out, outp,
                                                  B_ * S_, D_, D_);
    }
}

// round 17
// speedup vs baseline: 1.3719x; 1.3719x over previous
#include <cuda_runtime.h>
#include <cuda_bf16.h>
#include <cstdint>

#define B_  4
#define S_  2048
#define D_  1024
#define H_  16
#define HD_ 64
#define TD_ 3072   // 3*D
#define NQKV (B_ * H_ * S_ * HD_)   // 8,388,608

// ---------------- scratch: hi/lo bf16 split tensors --------------------------
__device__ __nv_bfloat16 g_xh[B_ * S_ * D_],  g_xl[B_ * S_ * D_];
__device__ __nv_bfloat16 g_wqh[TD_ * D_],     g_wql[TD_ * D_];
__device__ __nv_bfloat16 g_woh[D_ * D_],      g_wol[D_ * D_];
__device__ __nv_bfloat16 g_qh[NQKV], g_ql[NQKV];
__device__ __nv_bfloat16 g_kh[NQKV], g_kl[NQKV];
__device__ __nv_bfloat16 g_vh[NQKV], g_vl[NQKV];
__device__ __nv_bfloat16 g_vfh[B_ * S_ * D_], g_vfl[B_ * S_ * D_];

// ---------------- fast exp (5-FMA poly) --------------------------------------
__device__ __forceinline__ float fexp(float x) {
    x = fmaxf(x, -80.0f);
    float y = x * 1.44269504088896340736f;
    float t = y + 12582912.0f;
    int   i = __float_as_int(t) - 0x4b400000;
    float f = y - (t - 12582912.0f);
    float p =              1.33336500e-3f;
    p = fmaf(p, f,         9.61793571e-3f);
    p = fmaf(p, f,         5.55041086e-2f);
    p = fmaf(p, f,         2.40226507e-1f);
    p = fmaf(p, f,         6.93147181e-1f);
    p = fmaf(p, f,         1.0f);
    return __int_as_float(__float_as_int(p) + (i << 23));
}

// ---------------- helpers ----------------------------------------------------
__device__ __forceinline__ void split1(float x, __nv_bfloat16& h, __nv_bfloat16& l) {
    h = __float2bfloat16_rn(x);
    l = __float2bfloat16_rn(x - __bfloat162float(h));
}
__device__ __forceinline__ uint32_t pckh(__nv_bfloat16 a, __nv_bfloat16 b) {
    __nv_bfloat162 t = __halves2bfloat162(a, b);
    return *reinterpret_cast<uint32_t*>(&t);
}
__device__ __forceinline__ void mma16816(float c[4], const uint32_t a[4], const uint32_t b[2]) {
    asm volatile(
        "mma.sync.aligned.m16n8k16.row.col.f32.bf16.bf16.f32 "
        "{%0,%1,%2,%3}, {%4,%5,%6,%7}, {%8,%9}, {%0,%1,%2,%3};"
        : "+f"(c[0]), "+f"(c[1]), "+f"(c[2]), "+f"(c[3])
        : "r"(a[0]), "r"(a[1]), "r"(a[2]), "r"(a[3]), "r"(b[0]), "r"(b[1]));
}
__device__ __forceinline__ uint32_t smem_u32(const void* p) {
    uint32_t a;
    asm("{ .reg .u64 t; cvta.to.shared.u64 t, %1; cvt.u32.u64 %0, t; }" : "=r"(a) : "l"(p));
    return a;
}
__device__ __forceinline__ void cpa16(uint32_t d, const void* s) {
    asm volatile("cp.async.cg.shared.global [%0], [%1], 16;" :: "r"(d), "l"(s));
}
#define CP_COMMIT() asm volatile("cp.async.commit_group;" ::: "memory")
#define CP_WAIT0()  asm volatile("cp.async.wait_group 0;" ::: "memory")
#define CP_WAIT1()  asm volatile("cp.async.wait_group 1;" ::: "memory")

__device__ __forceinline__ void ldsm4(uint32_t* r, uint32_t a) {
    asm volatile("ldmatrix.sync.aligned.m8n8.x4.shared.b16 {%0,%1,%2,%3}, [%4];"
        : "=r"(r[0]), "=r"(r[1]), "=r"(r[2]), "=r"(r[3]) : "r"(a));
}
__device__ __forceinline__ void ldsm4t(uint32_t* r, uint32_t a) {
    asm volatile("ldmatrix.sync.aligned.m8n8.x4.trans.shared.b16 {%0,%1,%2,%3}, [%4];"
        : "=r"(r[0]), "=r"(r[1]), "=r"(r[2]), "=r"(r[3]) : "r"(a));
}

// ================= pre-split: fp32 -> (hi, lo) bf16 ==========================
__global__ void split_kernel(const float* __restrict__ src,
                             __nv_bfloat16* __restrict__ dh,
                             __nv_bfloat16* __restrict__ dl, int n4)
{
    int i = blockIdx.x * blockDim.x + threadIdx.x;
    if (i >= n4) return;
    float4 v = ((const float4*)src)[i];
    __nv_bfloat16 h0,h1,h2,h3,l0,l1,l2,l3;
    split1(v.x,h0,l0); split1(v.y,h1,l1); split1(v.z,h2,l2); split1(v.w,h3,l3);
    ((uint2*)dh)[i] = make_uint2(pckh(h0,h1), pckh(h2,h3));
    ((uint2*)dl)[i] = make_uint2(pckh(l0,l1), pckh(l2,l3));
}

// ===== HMMA split-bf16 GEMM: block tile 128(M)x64(N), warp tile 32x32 =======
// 256 threads, 3-stage cp.async, 2 CTAs/SM (natural reg fit ~100).
#define GSTK 40
// stage layout (rows of GSTK bf16): Ah[0,128) Al[128,256) Wh[256,320) Wl[320,384)
#define GSTAGE_ROWS 384
#define GSTAGE_ELEMS (GSTAGE_ROWS * GSTK)          // 15360
#define GSM_TOTAL (3 * GSTAGE_ELEMS * 2)           // 92160 bytes

template <int EPI>
__global__ void __launch_bounds__(256, 2)
hgemm_kernel(const __nv_bfloat16* __restrict__ Ah, const __nv_bfloat16* __restrict__ Al,
             const __nv_bfloat16* __restrict__ Wh, const __nv_bfloat16* __restrict__ Wl,
             const float* __restrict__ bias, float* __restrict__ C,
             int M, int N, int K)
{
    extern __shared__ __nv_bfloat16 gsm[];
    const uint32_t sb = smem_u32(gsm);

    const int tid = threadIdx.x;
    const int w = tid >> 5, lane = tid & 31;
    const int gid = lane >> 2, tig = lane & 3;
    const int wm = w & 3, wn = w >> 2;             // 4 x 2 warp grid (M x N)
    const int m0 = blockIdx.y * 128, n0 = blockIdx.x * 64;

    const int lr = tid >> 1;                        // 0..127
    const int lc = (tid & 1) * 16;                  // 0 or 16

    const uint32_t aoffG = (uint32_t)(((lane & 15) * GSTK + ((lane >> 4) << 3)) * 2);
    const uint32_t boffG = (uint32_t)(((((lane >> 4) << 3) + (lane & 7)) * GSTK
                                      + (((lane >> 3) & 1) << 3)) * 2);

    float acc[2][4][4];
#pragma unroll
    for (int mi = 0; mi < 2; mi++)
#pragma unroll
        for (int ni = 0; ni < 4; ni++)
            acc[mi][ni][0]=acc[mi][ni][1]=acc[mi][ni][2]=acc[mi][ni][3]=0.f;

    // global row sources for the 3 loader passes (128 logical rows each)
    const __nv_bfloat16* gsrc[3];
    gsrc[0] = Ah + (size_t)(m0 + lr) * K + lc;
    gsrc[1] = Al + (size_t)(m0 + lr) * K + lc;
    gsrc[2] = (lr < 64) ? (Wh + (size_t)(n0 + lr) * K + lc)
                        : (Wl + (size_t)(n0 + lr - 64) * K + lc);

    const int NIT = K / 32;
    auto issue = [&](int st, int k0) {
#pragma unroll
        for (int p = 0; p < 3; p++) {
            uint32_t d = sb + (uint32_t)((st * GSTAGE_ELEMS + (p * 128 + lr) * GSTK + lc) * 2);
            const __nv_bfloat16* s = gsrc[p] + k0;
            cpa16(d, s);
            cpa16(d + 16, s + 8);
        }
    };

    issue(0, 0);  CP_COMMIT();
    issue(1, 32); CP_COMMIT();

    for (int kt = 0; kt < NIT; kt++) {
        CP_WAIT1();
        __syncthreads();
        int ns = kt + 2;
        if (ns < NIT) issue(ns % 3, ns * 32);
        CP_COMMIT();

        const uint32_t stb  = sb + (uint32_t)((kt % 3) * GSTAGE_ELEMS * 2);
        const uint32_t stAh = stb;
        const uint32_t stAl = stb + (uint32_t)(128 * GSTK * 2);
        const uint32_t stWh = stb + (uint32_t)(256 * GSTK * 2);
        const uint32_t stWl = stb + (uint32_t)(320 * GSTK * 2);

#pragma unroll
        for (int kk = 0; kk < 2; kk++) {
            const int qc0 = kk * 16;
            uint32_t aH[2][4], aL[2][4];
#pragma unroll
            for (int mi = 0; mi < 2; mi++) {
                uint32_t ro = (uint32_t)(((wm * 32 + mi * 16) * GSTK + qc0) * 2);
                ldsm4(aH[mi], stAh + ro + aoffG);
                ldsm4(aL[mi], stAl + ro + aoffG);
            }
#pragma unroll
            for (int nj = 0; nj < 2; nj++) {
                uint32_t bh4[4], bl4[4];
                uint32_t no = (uint32_t)(((wn * 32 + nj * 16) * GSTK + qc0) * 2);
                ldsm4(bh4, stWh + no + boffG);
                ldsm4(bl4, stWl + no + boffG);
#pragma unroll
                for (int mi = 0; mi < 2; mi++) {
                    mma16816(acc[mi][2*nj],   aH[mi], bh4);
                    mma16816(acc[mi][2*nj],   aH[mi], bl4);
                    mma16816(acc[mi][2*nj],   aL[mi], bh4);
                    mma16816(acc[mi][2*nj+1], aH[mi], bh4 + 2);
                    mma16816(acc[mi][2*nj+1], aH[mi], bl4 + 2);
                    mma16816(acc[mi][2*nj+1], aL[mi], bh4 + 2);
                }
            }
        }
    }

    // epilogue
#pragma unroll
    for (int mi = 0; mi < 2; mi++) {
#pragma unroll
        for (int rr = 0; rr < 2; rr++) {
            int m = m0 + wm * 32 + mi * 16 + gid + rr * 8;
#pragma unroll
            for (int ni = 0; ni < 4; ni++) {
                int n = n0 + wn * 32 + ni * 8 + tig * 2;
                float v0 = acc[mi][ni][rr*2+0] + bias[n];
                float v1 = acc[mi][ni][rr*2+1] + bias[n+1];
                if (EPI == 0) {
                    *(float2*)(C + (size_t)m * N + n) = make_float2(v0, v1);
                } else {
                    int h  = n / 192;
                    int r2 = n - h * 192;
                    int wch = r2 >> 6;
                    int hd = r2 & 63;
                    int bb = m >> 11, ss = m & (S_ - 1);
                    size_t di = ((size_t)(bb * H_ + h) * S_ + ss) * HD_ + hd;
                    __nv_bfloat16* dh = (wch == 0) ? g_qh : (wch == 1) ? g_kh : g_vh;
                    __nv_bfloat16* dl = (wch == 0) ? g_ql : (wch == 1) ? g_kl : g_vl;
                    __nv_bfloat16 h0,h1,l0,l1;
                    split1(v0,h0,l0); split1(v1,h1,l1);
                    *(uint32_t*)(dh + di) = pckh(h0,h1);
                    *(uint32_t*)(dl + di) = pckh(l0,l1);
                }
            }
        }
    }
}

// ---------------- attention smem (bf16 elems), stride 72 ---------------------
// QH 9216 | QL 9216 | K 2 stages x (KH 4608 + KL 4608) | V 2 stages x (...)
#define STK 72
#define ASM_ELEMS 55296          // 110592 bytes

// ============ attention: HMMA split-bf16 + ldmatrix (R11 proven) ============
__global__ void __launch_bounds__(256)
attn_mma_kernel(float* __restrict__ gAttn, int writeAttn)
{
    extern __shared__ __nv_bfloat16 sm[];
    const uint32_t sb = smem_u32(sm);
    const uint32_t sbQH = sb, sbQL = sb + 18432;
    const uint32_t sbK  = sb + 36864;          // + st*18432 ; KL at +9216
    const uint32_t sbV  = sb + 73728;          // + st*18432 ; VL at +9216

    const int tid = threadIdx.x;
    const int w = tid >> 5, lane = tid & 31;
    const int gid = lane >> 2, tig = lane & 3;
    const int qt = blockIdx.x, bh = blockIdx.y;
    const int sq = qt * 128;

    const size_t qoff = ((size_t)bh * S_ + sq) * HD_;
    const size_t koff = (size_t)bh * S_ * HD_;

    const uint32_t aoff = (uint32_t)(((lane & 15) * STK + ((lane >> 4) << 3)) * 2);
    const uint32_t boff = (uint32_t)(((((lane >> 4) << 3) + (lane & 7)) * STK
                                     + (((lane >> 3) & 1) << 3)) * 2);
    const uint32_t voff = (uint32_t)((((((lane >> 3) & 1) << 3) + (lane & 7)) * STK
                                     + ((lane >> 4) << 3)) * 2);

    auto issueK = [&](int st, int t) {
        const __nv_bfloat16* kh = g_kh + koff + t * 4096;
        const __nv_bfloat16* kl = g_kl + koff + t * 4096;
        uint32_t base = sbK + st * 18432;
#pragma unroll
        for (int it = 0; it < 2; it++) {
            int c = it * 256 + tid;
            int row = c >> 3, k8 = (c & 7) * 8;
            uint32_t d = base + (uint32_t)((row * STK + k8) * 2);
            cpa16(d,        kh + row * 64 + k8);
            cpa16(d + 9216, kl + row * 64 + k8);
        }
    };
    auto issueV = [&](int st, int t) {
        const __nv_bfloat16* vh = g_vh + koff + t * 4096;
        const __nv_bfloat16* vl = g_vl + koff + t * 4096;
        uint32_t base = sbV + st * 18432;
#pragma unroll
        for (int it = 0; it < 2; it++) {
            int c = it * 256 + tid;
            int row = c >> 3, k8 = (c & 7) * 8;
            uint32_t d = base + (uint32_t)((row * STK + k8) * 2);
            cpa16(d,        vh + row * 64 + k8);
            cpa16(d + 9216, vl + row * 64 + k8);
        }
    };

    // ---- load Q tile (128x64) hi/lo to smem --------------------------------
    {
        __nv_bfloat16* Qhs = sm;
        __nv_bfloat16* Qls = sm + 9216;
#pragma unroll
        for (int it = 0; it < 8; it++) {
            int f4 = it * 256 + tid;
            int r = f4 >> 4, c = (f4 & 15) << 2;
            *(uint2*)&Qhs[r*STK + c] = ((const uint2*)(g_qh + qoff))[f4];
            *(uint2*)&Qls[r*STK + c] = ((const uint2*)(g_ql + qoff))[f4];
        }
    }
    issueK(0, 0); CP_COMMIT();
    __syncthreads();

    // ---- hoist Q fragments (loop-invariant) --------------------------------
    uint32_t qfh[4][4], qfl[4][4];
#pragma unroll
    for (int kc = 0; kc < 4; kc++) {
        uint32_t ro = (uint32_t)(((w * 16) * STK + kc * 16) * 2);
        ldsm4(qfh[kc], sbQH + ro + aoff);
        ldsm4(qfl[kc], sbQL + ro + aoff);
    }

    const int qr = w * 16 + gid;
    float m0 = -1e30f, m1 = -1e30f, l0s = 0.f, l1s = 0.f;

    // =================== pass 1: rowmax m, denom l ===========================
    for (int t = 0; t < 32; t++) {
        CP_WAIT0();
        __syncthreads();
        if (t + 1 < 32) issueK((t + 1) & 1, t + 1);
        CP_COMMIT();

        const uint32_t stKh = sbK + (t & 1) * 18432;
        const uint32_t stKl = stKh + 9216;

        float s[8][4];
#pragma unroll
        for (int nc = 0; nc < 8; nc++)
            s[nc][0]=s[nc][1]=s[nc][2]=s[nc][3]=0.f;

#pragma unroll
        for (int kc = 0; kc < 4; kc++) {
            const uint32_t co = (uint32_t)(kc * 16 * 2);
#pragma unroll
            for (int nj = 0; nj < 4; nj++) {
                uint32_t bh4[4], bl4[4];
                uint32_t no = (uint32_t)((nj * 16 * STK) * 2) + co;
                ldsm4(bh4, stKh + no + boff);
                ldsm4(bl4, stKl + no + boff);
                mma16816(s[2*nj],   qfh[kc], bh4);
                mma16816(s[2*nj],   qfh[kc], bl4);
                mma16816(s[2*nj],   qfl[kc], bh4);
                mma16816(s[2*nj+1], qfh[kc], bh4 + 2);
                mma16816(s[2*nj+1], qfh[kc], bl4 + 2);
                mma16816(s[2*nj+1], qfl[kc], bh4 + 2);
            }
        }

        float mx0 = -1e30f, mx1 = -1e30f;
#pragma unroll
        for (int nc = 0; nc < 8; nc++) {
            s[nc][0]*=0.125f; s[nc][1]*=0.125f; s[nc][2]*=0.125f; s[nc][3]*=0.125f;
            mx0 = fmaxf(mx0, fmaxf(s[nc][0], s[nc][1]));
            mx1 = fmaxf(mx1, fmaxf(s[nc][2], s[nc][3]));
        }
        mx0 = fmaxf(mx0, __shfl_xor_sync(0xffffffffu, mx0, 1));
        mx0 = fmaxf(mx0, __shfl_xor_sync(0xffffffffu, mx0, 2));
        mx1 = fmaxf(mx1, __shfl_xor_sync(0xffffffffu, mx1, 1));
        mx1 = fmaxf(mx1, __shfl_xor_sync(0xffffffffu, mx1, 2));
        float mn0 = fmaxf(m0, mx0), mn1 = fmaxf(m1, mx1);
        float ps0 = 0.f, ps1 = 0.f;
#pragma unroll
        for (int nc = 0; nc < 8; nc++) {
            ps0 += fexp(s[nc][0]-mn0) + fexp(s[nc][1]-mn0);
            ps1 += fexp(s[nc][2]-mn1) + fexp(s[nc][3]-mn1);
        }
        ps0 += __shfl_xor_sync(0xffffffffu, ps0, 1);
        ps0 += __shfl_xor_sync(0xffffffffu, ps0, 2);
        ps1 += __shfl_xor_sync(0xffffffffu, ps1, 1);
        ps1 += __shfl_xor_sync(0xffffffffu, ps1, 2);
        l0s = l0s * fexp(m0 - mn0) + ps0;  m0 = mn0;
        l1s = l1s * fexp(m1 - mn1) + ps1;  m1 = mn1;
    }
    const float invl0 = 1.0f / l0s;
    const float invl1 = 1.0f / l1s;

    float o[8][4];
#pragma unroll
    for (int nd = 0; nd < 8; nd++)
        o[nd][0]=o[nd][1]=o[nd][2]=o[nd][3]=0.f;

    issueK(0, 0); issueV(0, 0); CP_COMMIT();

    // =================== pass 2: normalized P out + O = P@V ==================
    for (int t = 0; t < 32; t++) {
        CP_WAIT0();
        __syncthreads();
        if (t + 1 < 32) { issueK((t + 1) & 1, t + 1); issueV((t + 1) & 1, t + 1); }
        CP_COMMIT();

        const uint32_t stKh = sbK + (t & 1) * 18432;
        const uint32_t stKl = stKh + 9216;
        const uint32_t stVh = sbV + (t & 1) * 18432;
        const uint32_t stVl = stVh + 9216;

        float s[8][4];
#pragma unroll
        for (int nc = 0; nc < 8; nc++)
            s[nc][0]=s[nc][1]=s[nc][2]=s[nc][3]=0.f;

#pragma unroll
        for (int kc = 0; kc < 4; kc++) {
            const uint32_t co = (uint32_t)(kc * 16 * 2);
#pragma unroll
            for (int nj = 0; nj < 4; nj++) {
                uint32_t bh4[4], bl4[4];
                uint32_t no = (uint32_t)((nj * 16 * STK) * 2) + co;
                ldsm4(bh4, stKh + no + boff);
                ldsm4(bl4, stKl + no + boff);
                mma16816(s[2*nj],   qfh[kc], bh4);
                mma16816(s[2*nj],   qfh[kc], bl4);
                mma16816(s[2*nj],   qfl[kc], bh4);
                mma16816(s[2*nj+1], qfh[kc], bh4 + 2);
                mma16816(s[2*nj+1], qfh[kc], bl4 + 2);
                mma16816(s[2*nj+1], qfl[kc], bh4 + 2);
            }
        }

#pragma unroll
        for (int nc = 0; nc < 8; nc++) {
            s[nc][0] = fexp(s[nc][0]*0.125f - m0) * invl0;
            s[nc][1] = fexp(s[nc][1]*0.125f - m0) * invl0;
            s[nc][2] = fexp(s[nc][2]*0.125f - m1) * invl1;
            s[nc][3] = fexp(s[nc][3]*0.125f - m1) * invl1;
        }

        if (writeAttn) {
            float* gA = gAttn + ((size_t)bh * S_ + sq + qr) * S_ + t*64 + tig*2;
#pragma unroll
            for (int nc = 0; nc < 8; nc++) {
                *(float2*)(gA + nc*8)        = make_float2(s[nc][0], s[nc][1]);
                *(float2*)(gA + 8*S_ + nc*8) = make_float2(s[nc][2], s[nc][3]);
            }
        }

        // PV: A-frags from S accumulators; B-frags via ldmatrix.trans on V
#pragma unroll
        for (int kc = 0; kc < 4; kc++) {
            uint32_t aH[4], aL[4];
            {
                const float* p0 = s[2*kc];
                const float* p1 = s[2*kc+1];
                __nv_bfloat16 h00,h01,h02,h03,h10,h11,h12,h13;
                __nv_bfloat16 q00,q01,q02,q03,q10,q11,q12,q13;
                split1(p0[0],h00,q00); split1(p0[1],h01,q01);
                split1(p0[2],h02,q02); split1(p0[3],h03,q03);
                split1(p1[0],h10,q10); split1(p1[1],h11,q11);
                split1(p1[2],h12,q12); split1(p1[3],h13,q13);
                aH[0]=pckh(h00,h01); aH[1]=pckh(h02,h03);
                aH[2]=pckh(h10,h11); aH[3]=pckh(h12,h13);
                aL[0]=pckh(q00,q01); aL[1]=pckh(q02,q03);
                aL[2]=pckh(q10,q11); aL[3]=pckh(q12,q13);
            }
            const uint32_t ko = (uint32_t)((kc * 16 * STK) * 2);
#pragma unroll
            for (int nj = 0; nj < 4; nj++) {
                uint32_t vh4[4], vl4[4];
                uint32_t no = ko + (uint32_t)(nj * 16 * 2);
                ldsm4t(vh4, stVh + no + voff);
                ldsm4t(vl4, stVl + no + voff);
                mma16816(o[2*nj],   aH, vh4);
                mma16816(o[2*nj],   aH, vl4);
                mma16816(o[2*nj],   aL, vh4);
                mma16816(o[2*nj+1], aH, vh4 + 2);
                mma16816(o[2*nj+1], aH, vl4 + 2);
                mma16816(o[2*nj+1], aL, vh4 + 2);
            }
        }
    }

    // O -> hi/lo bf16 in [B,H,S,hd] layout (== the buggy reshape) for out GEMM
    {
        size_t ob = ((size_t)bh * S_ + sq + qr) * HD_ + tig*2;
#pragma unroll
        for (int nd = 0; nd < 8; nd++) {
            __nv_bfloat16 h0,h1,h2,h3,l0,l1,l2,l3;
            split1(o[nd][0],h0,l0); split1(o[nd][1],h1,l1);
            split1(o[nd][2],h2,l2); split1(o[nd][3],h3,l3);
            *(uint32_t*)(g_vfh + ob + nd*8)          = pckh(h0,h1);
            *(uint32_t*)(g_vfl + ob + nd*8)          = pckh(l0,l1);
            *(uint32_t*)(g_vfh + ob + 8*HD_ + nd*8)  = pckh(h2,h3);
            *(uint32_t*)(g_vfl + ob + 8*HD_ + nd*8)  = pckh(l2,l3);
        }
    }
}

// ---------------------------------------------------------------------------
extern "C" void kernel_launch(void* const* d_in, const int* in_sizes, int n_in,
                              void* d_out, int out_size)
{
    const float* x     = (const float*)d_in[0];
    const float* w_qkv = (const float*)d_in[1];
    const float* b_qkv = (const float*)d_in[2];
    const float* w_out = (const float*)d_in[3];
    const float* b_out = (const float*)d_in[4];
    float* out = (float*)d_out;

    const long long BSD  = (long long)B_ * S_ * D_;
    const long long BHSS = (long long)B_ * H_ * S_ * S_;

    float* outp = nullptr;
    float* attnp = nullptr;
    int wA = 0;
    if ((long long)out_size >= BSD + BHSS) { outp = out; attnp = out + BSD; wA = 1; }
    else if ((long long)out_size == BHSS)  { attnp = out; wA = 1; }
    else                                   { outp = out; }

    cudaFuncSetAttribute(attn_mma_kernel, cudaFuncAttributeMaxDynamicSharedMemorySize,
                         ASM_ELEMS * (int)sizeof(__nv_bfloat16));
    cudaFuncSetAttribute(hgemm_kernel<0>, cudaFuncAttributeMaxDynamicSharedMemorySize,
                         GSM_TOTAL);
    cudaFuncSetAttribute(hgemm_kernel<1>, cudaFuncAttributeMaxDynamicSharedMemorySize,
                         GSM_TOTAL);

    __nv_bfloat16 *xh, *xl, *wqh, *wql, *woh, *wol, *vfh, *vfl;
    cudaGetSymbolAddress((void**)&xh,  g_xh);  cudaGetSymbolAddress((void**)&xl,  g_xl);
    cudaGetSymbolAddress((void**)&wqh, g_wqh); cudaGetSymbolAddress((void**)&wql, g_wql);
    cudaGetSymbolAddress((void**)&woh, g_woh); cudaGetSymbolAddress((void**)&wol, g_wol);
    cudaGetSymbolAddress((void**)&vfh, g_vfh); cudaGetSymbolAddress((void**)&vfl, g_vfl);

    // K0: pre-split fp32 -> hi/lo bf16
    {
        int n4x = (B_ * S_ * D_) / 4, n4q = (TD_ * D_) / 4, n4o = (D_ * D_) / 4;
        split_kernel<<<(n4x + 255) / 256, 256>>>(x,     xh,  xl,  n4x);
        split_kernel<<<(n4q + 255) / 256, 256>>>(w_qkv, wqh, wql, n4q);
        split_kernel<<<(n4o + 255) / 256, 256>>>(w_out, woh, wol, n4o);
    }
    // K1: fused QKV projection (HMMA, 128x64 tile, 2 CTA/SM)
    {
        dim3 grid(TD_ / 64, (B_ * S_) / 128);
        hgemm_kernel<1><<<grid, 256, GSM_TOTAL>>>(xh, xl, wqh, wql, b_qkv, nullptr,
                                                  B_ * S_, TD_, D_);
    }
    // K2: HMMA attention (R11 config)
    {
        dim3 grid(S_ / 128, B_ * H_);
        attn_mma_kernel<<<grid, 256, ASM_ELEMS * (int)sizeof(__nv_bfloat16)>>>(attnp, wA);
    }
    // K3: output projection
    if (outp) {
        dim3 grid(D_ / 64, (B_ * S_) / 128);
        hgemm_kernel<0><<<grid, 256, GSM_TOTAL>>>(vfh, vfl, woh, wol, b_out, outp,
                                                  B_ * S_, D_, D_);
    }
}